// round 1
// baseline (speedup 1.0000x reference)
#include <cuda_runtime.h>

// Problem constants
#define BB   64
#define KK   4
#define MM   3
#define NPIX 65536            // 256*256
#define NVEC (NPIX / 4)       // 16384 float4 vectors per (b, channel)
#define NVALS 16              // 12 num (k*3+m) + 4 den
#define BLOCKS_PER_B 16
#define THREADS 256
#define ITERS 4               // NVEC / (BLOCKS_PER_B*THREADS) = 16384/4096

// Scratch: per-batch partial sums. num at [b*16 + k*3 + m], den at [b*16 + 12 + k]
__device__ float g_scratch[BB * NVALS];

__global__ void zero_kernel() {
    int i = blockIdx.x * blockDim.x + threadIdx.x;
    if (i < BB * NVALS) g_scratch[i] = 0.0f;
}

__global__ __launch_bounds__(THREADS) void reduce_kernel(
    const float* __restrict__ pred,   // [B, K, X, Y]
    const float* __restrict__ inp,    // [B, M, X, Y]
    const int*   __restrict__ heart)  // [B, 1, X, Y]
{
    const int b   = blockIdx.x / BLOCKS_PER_B;
    const int blk = blockIdx.x % BLOCKS_PER_B;

    const float4* __restrict__ pred4  = (const float4*)pred;
    const float4* __restrict__ inp4   = (const float4*)inp;
    const int4*   __restrict__ heart4 = (const int4*)heart;

    // Per-thread accumulators
    float acc[NVALS];
    #pragma unroll
    for (int i = 0; i < NVALS; i++) acc[i] = 0.0f;

    const int vec_base = blk * (NVEC / BLOCKS_PER_B) + threadIdx.x;

    #pragma unroll
    for (int it = 0; it < ITERS; it++) {
        const int v = vec_base + it * THREADS;   // vec index within batch

        // Mask from heart
        int4 h = heart4[(long)b * NVEC + v];
        float m0 = (h.x == 1) ? 1.0f : 0.0f;
        float m1 = (h.y == 1) ? 1.0f : 0.0f;
        float m2 = (h.z == 1) ? 1.0f : 0.0f;
        float m3 = (h.w == 1) ? 1.0f : 0.0f;

        // Inputs (3 channels)
        float4 in_v[MM];
        #pragma unroll
        for (int m = 0; m < MM; m++)
            in_v[m] = inp4[((long)b * MM + m) * NVEC + v];

        // Predictions (4 channels), masked, accumulate den and num
        #pragma unroll
        for (int k = 0; k < KK; k++) {
            float4 p = pred4[((long)b * KK + k) * NVEC + v];
            float p0 = p.x * m0, p1 = p.y * m1, p2 = p.z * m2, p3 = p.w * m3;
            acc[12 + k] += (p0 + p1) + (p2 + p3);
            #pragma unroll
            for (int m = 0; m < MM; m++) {
                acc[k * MM + m] = fmaf(p0, in_v[m].x,
                                  fmaf(p1, in_v[m].y,
                                  fmaf(p2, in_v[m].z,
                                  fmaf(p3, in_v[m].w, acc[k * MM + m]))));
            }
        }
    }

    // Warp reduction of all 16 accumulators
    #pragma unroll
    for (int i = 0; i < NVALS; i++) {
        float v = acc[i];
        #pragma unroll
        for (int o = 16; o > 0; o >>= 1)
            v += __shfl_down_sync(0xffffffffu, v, o);
        acc[i] = v;
    }

    // Cross-warp: smem accumulate then one atomicAdd per value
    __shared__ float s_acc[NVALS];
    if (threadIdx.x < NVALS) s_acc[threadIdx.x] = 0.0f;
    __syncthreads();
    if ((threadIdx.x & 31) == 0) {
        #pragma unroll
        for (int i = 0; i < NVALS; i++)
            atomicAdd(&s_acc[i], acc[i]);
    }
    __syncthreads();
    if (threadIdx.x < NVALS)
        atomicAdd(&g_scratch[b * NVALS + threadIdx.x], s_acc[threadIdx.x]);
}

__global__ void finalize_kernel(const float* __restrict__ mu_data,
                                float* __restrict__ out)
{
    const int i = threadIdx.x;     // one warp
    float v = 0.0f;
    if (i < KK * MM) {
        const int k = i / MM, m = i % MM;
        float s = 0.0f;
        for (int b = 0; b < BB; b++) {
            float den = g_scratch[b * NVALS + 12 + k] + 1e-10f;
            s += g_scratch[b * NVALS + k * MM + m] / den;
        }
        float mu_mean = s * (1.0f / (float)BB);
        float d = mu_data[k * MM + m] - mu_mean;
        v = d * d;
    }
    #pragma unroll
    for (int o = 16; o > 0; o >>= 1)
        v += __shfl_down_sync(0xffffffffu, v, o);
    if (i == 0) out[0] = v;
}

extern "C" void kernel_launch(void* const* d_in, const int* in_sizes, int n_in,
                              void* d_out, int out_size)
{
    const float* pred    = (const float*)d_in[0];
    const float* inp     = (const float*)d_in[1];
    const int*   heart   = (const int*)d_in[2];
    const float* mu_data = (const float*)d_in[3];
    float* out = (float*)d_out;

    zero_kernel<<<1, BB * NVALS>>>();
    reduce_kernel<<<BB * BLOCKS_PER_B, THREADS>>>(pred, inp, heart);
    finalize_kernel<<<1, 32>>>(mu_data, out);
}

// round 2
// speedup vs baseline: 1.2302x; 1.2302x over previous
#include <cuda_runtime.h>

// Problem constants
#define BB   64
#define KK   4
#define MM   3
#define NPIX 65536            // 256*256
#define NVEC (NPIX / 4)       // 16384 float4 vectors per (b, channel)
#define NVALS 16              // 12 num (k*3+m) + 4 den
#define BLOCKS_PER_B 16
#define THREADS 256
#define ITERS 4               // NVEC / (BLOCKS_PER_B*THREADS)
#define GRID (BB * BLOCKS_PER_B)

// Unique per-block partial sums: [block][16]. Plain stores, no zeroing needed.
__device__ float g_part[GRID * NVALS];
__device__ unsigned int g_counter = 0;   // self-resets to 0 every run

__global__ __launch_bounds__(THREADS) void fused_kernel(
    const float* __restrict__ pred,    // [B, K, X, Y]
    const float* __restrict__ inp,     // [B, M, X, Y]
    const int*   __restrict__ heart,   // [B, 1, X, Y]
    const float* __restrict__ mu_data, // [K, M]
    float*       __restrict__ out)     // scalar
{
    const int b   = blockIdx.x / BLOCKS_PER_B;
    const int blk = blockIdx.x % BLOCKS_PER_B;

    const float4* __restrict__ pred4  = (const float4*)pred;
    const float4* __restrict__ inp4   = (const float4*)inp;
    const int4*   __restrict__ heart4 = (const int4*)heart;

    float acc[NVALS];
    #pragma unroll
    for (int i = 0; i < NVALS; i++) acc[i] = 0.0f;

    const int vec_base = blk * (NVEC / BLOCKS_PER_B) + threadIdx.x;

    #pragma unroll
    for (int it = 0; it < ITERS; it++) {
        const int v = vec_base + it * THREADS;

        int4 h = heart4[(long)b * NVEC + v];
        float m0 = (h.x == 1) ? 1.0f : 0.0f;
        float m1 = (h.y == 1) ? 1.0f : 0.0f;
        float m2 = (h.z == 1) ? 1.0f : 0.0f;
        float m3 = (h.w == 1) ? 1.0f : 0.0f;

        float4 in_v[MM];
        #pragma unroll
        for (int m = 0; m < MM; m++)
            in_v[m] = inp4[((long)b * MM + m) * NVEC + v];

        #pragma unroll
        for (int k = 0; k < KK; k++) {
            float4 p = pred4[((long)b * KK + k) * NVEC + v];
            float p0 = p.x * m0, p1 = p.y * m1, p2 = p.z * m2, p3 = p.w * m3;
            acc[12 + k] += (p0 + p1) + (p2 + p3);
            #pragma unroll
            for (int m = 0; m < MM; m++) {
                acc[k * MM + m] = fmaf(p0, in_v[m].x,
                                  fmaf(p1, in_v[m].y,
                                  fmaf(p2, in_v[m].z,
                                  fmaf(p3, in_v[m].w, acc[k * MM + m]))));
            }
        }
    }

    // Warp reduction of all 16 accumulators
    #pragma unroll
    for (int i = 0; i < NVALS; i++) {
        float v = acc[i];
        #pragma unroll
        for (int o = 16; o > 0; o >>= 1)
            v += __shfl_down_sync(0xffffffffu, v, o);
        acc[i] = v;
    }

    // Cross-warp accumulate in smem, then plain store to unique slot
    __shared__ float s_acc[NVALS];
    __shared__ bool  s_is_last;
    if (threadIdx.x < NVALS) s_acc[threadIdx.x] = 0.0f;
    __syncthreads();
    if ((threadIdx.x & 31) == 0) {
        #pragma unroll
        for (int i = 0; i < NVALS; i++)
            atomicAdd(&s_acc[i], acc[i]);
    }
    __syncthreads();
    if (threadIdx.x < NVALS)
        g_part[blockIdx.x * NVALS + threadIdx.x] = s_acc[threadIdx.x];

    // Last-block-done detection
    __threadfence();
    if (threadIdx.x == 0) {
        unsigned int old = atomicAdd(&g_counter, 1u);
        s_is_last = (old == (unsigned)(GRID - 1));
    }
    __syncthreads();
    if (!s_is_last) return;

    // ---- finalize (one block; partials are L2-resident) ----
    __shared__ float s_sum[BB][NVALS];   // 4 KB
    for (int idx = threadIdx.x; idx < BB * NVALS; idx += THREADS) {
        const int bb = idx / NVALS, j = idx % NVALS;
        float s = 0.0f;
        #pragma unroll
        for (int p = 0; p < BLOCKS_PER_B; p++)
            s += g_part[(bb * BLOCKS_PER_B + p) * NVALS + j];
        s_sum[bb][j] = s;
    }
    __syncthreads();

    float v = 0.0f;
    if (threadIdx.x < KK * MM) {
        const int k = threadIdx.x / MM, m = threadIdx.x % MM;
        float s = 0.0f;
        for (int bb = 0; bb < BB; bb++) {
            const float den = s_sum[bb][12 + k] + 1e-10f;
            s += s_sum[bb][k * MM + m] / den;
        }
        const float mu_mean = s * (1.0f / (float)BB);
        const float d = mu_data[k * MM + m] - mu_mean;
        v = d * d;
    }
    if (threadIdx.x < 32) {
        #pragma unroll
        for (int o = 16; o > 0; o >>= 1)
            v += __shfl_down_sync(0xffffffffu, v, o);
        if (threadIdx.x == 0) {
            out[0] = v;
            g_counter = 0;   // reset for next (graph-replayed) run
        }
    }
}

extern "C" void kernel_launch(void* const* d_in, const int* in_sizes, int n_in,
                              void* d_out, int out_size)
{
    const float* pred    = (const float*)d_in[0];
    const float* inp     = (const float*)d_in[1];
    const int*   heart   = (const int*)d_in[2];
    const float* mu_data = (const float*)d_in[3];
    float* out = (float*)d_out;

    fused_kernel<<<GRID, THREADS>>>(pred, inp, heart, mu_data, out);
}

// round 4
// speedup vs baseline: 1.2391x; 1.0072x over previous
#include <cuda_runtime.h>

// Problem constants
#define BB   64
#define KK   4
#define MM   3
#define NPIX 65536            // 256*256
#define NVEC (NPIX / 4)       // 16384 float4 vectors per (b, channel)
#define NVALS 16              // 12 num (k*3+m) + 4 den
#define BLOCKS_PER_B 32
#define THREADS 256
#define NWARPS (THREADS / 32)
#define ITERS 2               // NVEC / (BLOCKS_PER_B*THREADS) = 16384/8192
#define GRID (BB * BLOCKS_PER_B)

// Unique per-block partial sums: [block][16]. Plain stores, no zeroing needed.
__device__ float g_part[GRID * NVALS];
__device__ unsigned int g_counter = 0;   // self-resets to 0 every run

__global__ __launch_bounds__(THREADS, 5) void fused_kernel(
    const float* __restrict__ pred,    // [B, K, X, Y]
    const float* __restrict__ inp,     // [B, M, X, Y]
    const int*   __restrict__ heart,   // [B, 1, X, Y]
    const float* __restrict__ mu_data, // [K, M]
    float*       __restrict__ out)     // scalar
{
    const int b   = blockIdx.x / BLOCKS_PER_B;
    const int blk = blockIdx.x % BLOCKS_PER_B;

    const float4* __restrict__ pred4  = (const float4*)pred;
    const float4* __restrict__ inp4   = (const float4*)inp;
    const int4*   __restrict__ heart4 = (const int4*)heart;

    float acc[NVALS];
    #pragma unroll
    for (int i = 0; i < NVALS; i++) acc[i] = 0.0f;

    const int vec_base = blk * (NVEC / BLOCKS_PER_B) + threadIdx.x;

    #pragma unroll
    for (int it = 0; it < ITERS; it++) {
        const int v = vec_base + it * THREADS;

        int4 h = heart4[(long)b * NVEC + v];
        float m0 = (h.x == 1) ? 1.0f : 0.0f;
        float m1 = (h.y == 1) ? 1.0f : 0.0f;
        float m2 = (h.z == 1) ? 1.0f : 0.0f;
        float m3 = (h.w == 1) ? 1.0f : 0.0f;

        float4 in_v[MM];
        #pragma unroll
        for (int m = 0; m < MM; m++)
            in_v[m] = inp4[((long)b * MM + m) * NVEC + v];

        #pragma unroll
        for (int k = 0; k < KK; k++) {
            float4 p = pred4[((long)b * KK + k) * NVEC + v];
            float p0 = p.x * m0, p1 = p.y * m1, p2 = p.z * m2, p3 = p.w * m3;
            acc[12 + k] += (p0 + p1) + (p2 + p3);
            #pragma unroll
            for (int m = 0; m < MM; m++) {
                acc[k * MM + m] = fmaf(p0, in_v[m].x,
                                  fmaf(p1, in_v[m].y,
                                  fmaf(p2, in_v[m].z,
                                  fmaf(p3, in_v[m].w, acc[k * MM + m]))));
            }
        }
    }

    // Warp reduction of all 16 accumulators
    #pragma unroll
    for (int i = 0; i < NVALS; i++) {
        float v = acc[i];
        #pragma unroll
        for (int o = 16; o > 0; o >>= 1)
            v += __shfl_down_sync(0xffffffffu, v, o);
        acc[i] = v;
    }

    // Cross-warp: plain STS per warp, then 16-thread gather (no smem atomics)
    __shared__ float s_part[NWARPS][NVALS];
    __shared__ bool  s_is_last;
    const int lane = threadIdx.x & 31;
    const int wid  = threadIdx.x >> 5;
    if (lane == 0) {
        #pragma unroll
        for (int i = 0; i < NVALS; i++)
            s_part[wid][i] = acc[i];
    }
    __syncthreads();
    if (threadIdx.x < NVALS) {
        float s = 0.0f;
        #pragma unroll
        for (int w = 0; w < NWARPS; w++)
            s += s_part[w][threadIdx.x];
        g_part[blockIdx.x * NVALS + threadIdx.x] = s;
    }

    // Last-block-done detection
    __threadfence();
    if (threadIdx.x == 0) {
        unsigned int old = atomicAdd(&g_counter, 1u);
        s_is_last = (old == (unsigned)(GRID - 1));
    }
    __syncthreads();
    if (!s_is_last) return;

    // ---- finalize (one block; partials are L2-resident) ----
    __shared__ float s_sum[BB][NVALS];   // 4 KB
    for (int idx = threadIdx.x; idx < BB * NVALS; idx += THREADS) {
        const int bb = idx / NVALS, j = idx % NVALS;
        float s = 0.0f;
        #pragma unroll
        for (int p = 0; p < BLOCKS_PER_B; p++)
            s += g_part[(bb * BLOCKS_PER_B + p) * NVALS + j];
        s_sum[bb][j] = s;
    }
    __syncthreads();

    float v = 0.0f;
    if (threadIdx.x < KK * MM) {
        const int k = threadIdx.x / MM, m = threadIdx.x % MM;
        float s = 0.0f;
        for (int bb = 0; bb < BB; bb++) {
            const float den = s_sum[bb][12 + k] + 1e-10f;
            s += s_sum[bb][k * MM + m] / den;
        }
        const float mu_mean = s * (1.0f / (float)BB);
        const float d = mu_data[k * MM + m] - mu_mean;
        v = d * d;
    }
    if (threadIdx.x < 32) {
        #pragma unroll
        for (int o = 16; o > 0; o >>= 1)
            v += __shfl_down_sync(0xffffffffu, v, o);
        if (threadIdx.x == 0) {
            out[0] = v;
            g_counter = 0;   // reset for next (graph-replayed) run
        }
    }
}

extern "C" void kernel_launch(void* const* d_in, const int* in_sizes, int n_in,
                              void* d_out, int out_size)
{
    const float* pred    = (const float*)d_in[0];
    const float* inp     = (const float*)d_in[1];
    const int*   heart   = (const int*)d_in[2];
    const float* mu_data = (const float*)d_in[3];
    float* out = (float*)d_out;

    fused_kernel<<<GRID, THREADS>>>(pred, inp, heart, mu_data, out);
}